// round 10
// baseline (speedup 1.0000x reference)
#include <cuda_runtime.h>

// VQ-VAE quantizer, round 10: k-pair f32x2 packing (zero lane swaps) +
// exact-argmin guarantee via margin screen + exact sequential rescue.
//   h: (256,512,32) f32 -> 131072 tokens x 32;  embeddings: (1024,32) f32
//   out f32: qst (131072*32) | indices (131072) | loss (131072)

typedef unsigned long long u64; typedef unsigned int u32;

#define DIM    32
#define NCODES 1024
#define NTOK   131072
#define TPB    224          // 7 warps
#define NBLK   148          // one CTA per SM
#define TOKPB  886          // 148*886 >= 131072 (tail clamped, dup writes identical)
#define TPT    4

__device__ __forceinline__ u64 pk2(float lo, float hi) {
    u64 r;
    asm("mov.b64 %0, {%1, %2};" : "=l"(r) : "f"(lo), "f"(hi));
    return r;
}
__device__ __forceinline__ void upk2(u64 v, float& lo, float& hi) {
    asm("mov.b64 {%0, %1}, %2;" : "=f"(lo), "=f"(hi) : "l"(v));
}
__device__ __forceinline__ u64 ffma2(u64 a, u64 b, u64 c) {
    u64 d;
    asm("fma.rn.f32x2 %0, %1, %2, %3;" : "=l"(d) : "l"(a), "l"(b), "l"(c));
    return d;
}
__device__ __forceinline__ u64 pkkey(float k, int i) {   // key in hi, idx in lo
    u64 r;
    asm("mov.b64 %0, {%1, %2};" : "=l"(r) : "r"((u32)i), "r"(__float_as_uint(k)));
    return r;
}
__device__ __forceinline__ float keyof(u64 p) { return __uint_as_float((u32)(p >> 32)); }
__device__ __forceinline__ u64 umin64(u64 a, u64 b) { return a < b ? a : b; }

// ||x||^2, reference-order reduction (R5-verified bit-exact).
__device__ __forceinline__ float sumsq32(const float* x) {
    float A0 = __fmul_rn(x[0], x[0]), A1 = __fmul_rn(x[1], x[1]);
    float A2 = __fmul_rn(x[2], x[2]), A3 = __fmul_rn(x[3], x[3]);
#pragma unroll
    for (int i = 1; i < 8; i++) {
        A0 = __fadd_rn(A0, __fmul_rn(x[4*i+0], x[4*i+0]));
        A1 = __fadd_rn(A1, __fmul_rn(x[4*i+1], x[4*i+1]));
        A2 = __fadd_rn(A2, __fmul_rn(x[4*i+2], x[4*i+2]));
        A3 = __fadd_rn(A3, __fmul_rn(x[4*i+3], x[4*i+3]));
    }
    return __fadd_rn(__fadd_rn(A0, A1), __fadd_rn(A2, A3));
}
__device__ __forceinline__ float sumsqdiff32(const float* q, const float* h) {
    float A0, A1, A2, A3;
    {
        float d0 = __fsub_rn(q[0], h[0]), d1 = __fsub_rn(q[1], h[1]);
        float d2 = __fsub_rn(q[2], h[2]), d3 = __fsub_rn(q[3], h[3]);
        A0 = __fmul_rn(d0, d0); A1 = __fmul_rn(d1, d1);
        A2 = __fmul_rn(d2, d2); A3 = __fmul_rn(d3, d3);
    }
#pragma unroll
    for (int i = 1; i < 8; i++) {
        float e0 = __fsub_rn(q[4*i+0], h[4*i+0]), e1 = __fsub_rn(q[4*i+1], h[4*i+1]);
        float e2 = __fsub_rn(q[4*i+2], h[4*i+2]), e3 = __fsub_rn(q[4*i+3], h[4*i+3]);
        A0 = __fadd_rn(A0, __fmul_rn(e0, e0));
        A1 = __fadd_rn(A1, __fmul_rn(e1, e1));
        A2 = __fadd_rn(A2, __fmul_rn(e2, e2));
        A3 = __fadd_rn(A3, __fmul_rn(e3, e3));
    }
    return __fadd_rn(__fadd_rn(A0, A1), __fadd_rn(A2, A3));
}

extern __shared__ float smf[];   // sE[1024][32] natural layout, then bn[1024]

__global__ void __launch_bounds__(TPB, 1)
vq_kernel(const float* __restrict__ H, const float* __restrict__ E,
          float* __restrict__ out) {
    float* sE = smf;
    float* bn = smf + NCODES * DIM;
    const int tid = threadIdx.x, lane = tid & 31;

    // ---- embedding table -> smem (natural layout) + exact norms ----
    for (int r = tid; r < NCODES; r += TPB) {
        float e[DIM];
        const float4* ep = (const float4*)(E + (size_t)r * DIM);
        float4* sp = (float4*)(sE + (size_t)r * DIM);
#pragma unroll
        for (int v = 0; v < 8; v++) {
            float4 x = ep[v];
            sp[v] = x;
            e[4*v+0] = x.x; e[4*v+1] = x.y; e[4*v+2] = x.z; e[4*v+3] = x.w;
        }
        bn[r] = sumsq32(e);
    }

    // ---- 4 tokens: h as k-pair packed u64 (natural order, zero MOVs) ----
    int tk[TPT];
#pragma unroll
    for (int t = 0; t < TPT; t++) {
        int x = blockIdx.x * TOKPB + tid * TPT + t;
        tk[t] = x < NTOK ? x : NTOK - 1;
    }
    u64 hk[TPT][16];
    float a[TPT];
#pragma unroll
    for (int t = 0; t < TPT; t++) {
        float h[DIM];
        const float4* hp = (const float4*)(H + (size_t)tk[t] * DIM);
#pragma unroll
        for (int v = 0; v < 8; v++) {
            float4 x = hp[v];
            h[4*v+0] = x.x; h[4*v+1] = x.y; h[4*v+2] = x.z; h[4*v+3] = x.w;
            hk[t][2*v]   = pk2(x.x, x.y);
            hk[t][2*v+1] = pk2(x.z, x.w);
        }
        a[t] = sumsq32(h);
    }
    __syncthreads();

    // ---- screen: packed min + lazily-captured runner-up ----
    const float INFP = __int_as_float(0x7f800000);
    u64 m1p[TPT];
    float m2[TPT];
#pragma unroll
    for (int t = 0; t < TPT; t++) { m1p[t] = pkkey(INFP, 0); m2[t] = INFP; }

#pragma unroll 1
    for (int c = 0; c < NCODES; c += 4) {
        const ulonglong2* e0 = (const ulonglong2*)(sE + (size_t)(c + 0) * DIM);
        const ulonglong2* e1 = (const ulonglong2*)(sE + (size_t)(c + 1) * DIM);
        const ulonglong2* e2 = (const ulonglong2*)(sE + (size_t)(c + 2) * DIM);
        const ulonglong2* e3 = (const ulonglong2*)(sE + (size_t)(c + 3) * DIM);

        u64 acc[TPT][4];
#pragma unroll
        for (int t = 0; t < TPT; t++)
#pragma unroll
            for (int cc = 0; cc < 4; cc++) acc[t][cc] = 0;

#pragma unroll
        for (int jj = 0; jj < 8; jj++) {
            ulonglong2 v0 = e0[jj], v1 = e1[jj], v2 = e2[jj], v3 = e3[jj];
#pragma unroll
            for (int t = 0; t < TPT; t++) {
                const u64 ha = hk[t][2*jj], hb = hk[t][2*jj+1];
                acc[t][0] = ffma2(v0.y, hb, ffma2(v0.x, ha, acc[t][0]));
                acc[t][1] = ffma2(v1.y, hb, ffma2(v1.x, ha, acc[t][1]));
                acc[t][2] = ffma2(v2.y, hb, ffma2(v2.x, ha, acc[t][2]));
                acc[t][3] = ffma2(v3.y, hb, ffma2(v3.x, ha, acc[t][3]));
            }
        }

        const float4 b4 = *(const float4*)(bn + c);
#pragma unroll
        for (int t = 0; t < TPT; t++) {
            float kv[4];
            u64 kp[4];
#pragma unroll
            for (int cc = 0; cc < 4; cc++) {
                float lo, hi;
                upk2(acc[t][cc], lo, hi);
                float dot = __fadd_rn(lo, hi);
                kv[cc] = __fmaf_rn(dot, -2.0f, __fadd_rn(a[t], (&b4.x)[cc]));
                kp[cc] = pkkey(kv[cc], c + cc);
            }
            u64 tm = umin64(umin64(kp[0], kp[1]), umin64(kp[2], kp[3]));
            u64 old = m1p[t];
            u64 nm  = umin64(old, tm);
            m1p[t]  = nm;
            float m1v = keyof(nm);
            float thr = __fmaf_rn(m1v, 4.8e-7f, 2e-7f);
            if (keyof(tm) <= __fadd_rn(m1v, thr)) {      // flagged tile (rare)
                if (nm != old) m2[t] = fminf(m2[t], keyof(old));
#pragma unroll
                for (int cc = 0; cc < 4; cc++)
                    if (kp[cc] != nm) m2[t] = fminf(m2[t], kv[cc]);
            }
        }
    }

    // ---- ambiguity + exact sequential rescue (warp-cooperative) ----
    int i1[TPT], amb[TPT];
#pragma unroll
    for (int t = 0; t < TPT; t++) {
        i1[t] = (int)(u32)m1p[t];
        float m1v = keyof(m1p[t]);
        amb[t] = m2[t] <= __fadd_rn(m1v, __fmaf_rn(m1v, 4.8e-7f, 2e-7f));
    }

#pragma unroll
    for (int t = 0; t < TPT; t++) {
        u32 bal = __ballot_sync(0xffffffffu, amb[t]);
        while (bal) {
            const int src = __ffs(bal) - 1;
            bal &= bal - 1;
            float hr[DIM];
#pragma unroll
            for (int j = 0; j < 16; j++) {
                u64 v = __shfl_sync(0xffffffffu, hk[t][j], src);
                upk2(v, hr[2*j], hr[2*j+1]);
            }
            const float at = __shfl_sync(0xffffffffu, a[t], src);
            float bd = INFP;
            int bix = 0;
#pragma unroll 1
            for (int w = 0; w < 32; w++) {
                const int code = lane + 32 * w;
                const float4* er = (const float4*)(E + (size_t)code * DIM);
                float acc = 0.0f;                 // reference sequential chain
#pragma unroll
                for (int v = 0; v < 8; v++) {
                    float4 x = er[v];
                    acc = __fmaf_rn(x.x, hr[4*v+0], acc);
                    acc = __fmaf_rn(x.y, hr[4*v+1], acc);
                    acc = __fmaf_rn(x.z, hr[4*v+2], acc);
                    acc = __fmaf_rn(x.w, hr[4*v+3], acc);
                }
                float dd = __fmaf_rn(acc, -2.0f, __fadd_rn(at, bn[code]));
                if (dd < bd) { bd = dd; bix = code; }   // strict <: first idx
            }
#pragma unroll
            for (int o = 16; o; o >>= 1) {
                float od = __shfl_xor_sync(0xffffffffu, bd, o);
                int   oi = __shfl_xor_sync(0xffffffffu, bix, o);
                if (od < bd || (od == bd && oi < bix)) { bd = od; bix = oi; }
            }
            if (lane == src) i1[t] = bix;
        }
    }

    // ---- exact outputs (identical fp32 math to R5) ----
#pragma unroll
    for (int t = 0; t < TPT; t++) {
        float h[DIM], q[DIM];
#pragma unroll
        for (int j = 0; j < 16; j++) upk2(hk[t][j], h[2*j], h[2*j+1]);
        const float4* qp = (const float4*)(sE + (size_t)i1[t] * DIM);
#pragma unroll
        for (int v = 0; v < 8; v++) {
            float4 x = qp[v];
            q[4*v+0] = x.x; q[4*v+1] = x.y; q[4*v+2] = x.z; q[4*v+3] = x.w;
        }
        float ss = sumsqdiff32(q, h);
        float L  = __fmul_rn(ss, 0.03125f);
        float l1 = __fmul_rn(L, 0.1f);
        float loss = __fadd_rn(l1, l1);

        float4* oq = (float4*)(out + (size_t)tk[t] * DIM);
#pragma unroll
        for (int v = 0; v < 8; v++) {
            float4 r;
            r.x = __fadd_rn(h[4*v+0], __fsub_rn(q[4*v+0], h[4*v+0]));
            r.y = __fadd_rn(h[4*v+1], __fsub_rn(q[4*v+1], h[4*v+1]));
            r.z = __fadd_rn(h[4*v+2], __fsub_rn(q[4*v+2], h[4*v+2]));
            r.w = __fadd_rn(h[4*v+3], __fsub_rn(q[4*v+3], h[4*v+3]));
            oq[v] = r;
        }
        out[(size_t)NTOK * DIM + tk[t]] = (float)i1[t];
        out[(size_t)NTOK * DIM + NTOK + tk[t]] = loss;
    }
}

extern "C" void kernel_launch(void* const* d_in, const int* in_sizes, int n_in,
                              void* d_out, int out_size) {
    (void)in_sizes; (void)n_in; (void)out_size;
    size_t smem = (size_t)(NCODES * DIM + NCODES) * sizeof(float);  // 135168 B
    cudaFuncSetAttribute(vq_kernel, cudaFuncAttributeMaxDynamicSharedMemorySize,
                         (int)smem);
    vq_kernel<<<NBLK, TPB, smem>>>((const float*)d_in[0], (const float*)d_in[1],
                                   (float*)d_out);
}

// round 11
// speedup vs baseline: 1.1535x; 1.1535x over previous
#include <cuda_runtime.h>

// VQ-VAE quantizer, round 11: occupancy attack.
//   h: (256,512,32) f32 -> 131072 tokens x 32;  embeddings: (1024,32) f32
//   out f32: qst (131072*32) | indices (131072) | loss (131072)
//
// Diagnosis: all prior variants ~100K instr/thread, issue stuck at 0.43 with
// 7-8 warps/SM (132KB full code table -> 1 CTA/SM). Fix: hold only a QUARTER
// of the code table (256 codes) in smem at a time, duplicated-lane layout
// (e,e) so token-pair f32x2 FFMA2 needs ZERO lane swaps; 70KB/CTA -> 2 CTAs
// per SM -> 16 warps/SM. 4 passes over code halves; argmin merged across
// passes in ascending code order (strict <).
//
// Arithmetic: identical fp32 expression tree to the R5-verified kernel
// (sequential ascending-k FMA chain per dot, reference-order norms,
// key = fl(fl(a+b) - 2*dot), strict-< first-index argmin, exact loss/qst).
// f32x2 lanes are IEEE-scalar-identical.

typedef unsigned long long u64;
typedef unsigned int u32;

#define DIM    32
#define NCODES 1024
#define NTOK   131072
#define TPB    256
#define TPT    2
#define NBLK   296          // 2 CTAs per SM x 148 SMs
#define TOKPB  443          // ceil(131072/296); threads cover 512 w/ overlap
#define CPP    256          // codes per pass
#define NPASS  (NCODES / CPP)
#define ROWB   272          // padded row stride (16B-aligned, 2-way build conflict)
#define BN_O   (CPP * ROWB) // 69632: dup norms u64[256]
#define SMEMSZ (BN_O + CPP * 8)  // 71680 B

__device__ __forceinline__ u64 pk2(float lo, float hi) {
    u64 r;
    asm("mov.b64 %0, {%1, %2};" : "=l"(r) : "f"(lo), "f"(hi));
    return r;
}
__device__ __forceinline__ void upk2(u64 v, float& lo, float& hi) {
    asm("mov.b64 {%0, %1}, %2;" : "=f"(lo), "=f"(hi) : "l"(v));
}
__device__ __forceinline__ u64 ffma2(u64 a, u64 b, u64 c) {
    u64 d;
    asm("fma.rn.f32x2 %0, %1, %2, %3;" : "=l"(d) : "l"(a), "l"(b), "l"(c));
    return d;
}
__device__ __forceinline__ u64 fadd2(u64 a, u64 b) {
    u64 d;
    asm("add.rn.f32x2 %0, %1, %2;" : "=l"(d) : "l"(a), "l"(b));
    return d;
}

// ||x||^2, reference-order reduction (R5-verified).
__device__ __forceinline__ float sumsq32(const float* x) {
    float A0 = __fmul_rn(x[0], x[0]), A1 = __fmul_rn(x[1], x[1]);
    float A2 = __fmul_rn(x[2], x[2]), A3 = __fmul_rn(x[3], x[3]);
#pragma unroll
    for (int i = 1; i < 8; i++) {
        A0 = __fadd_rn(A0, __fmul_rn(x[4*i+0], x[4*i+0]));
        A1 = __fadd_rn(A1, __fmul_rn(x[4*i+1], x[4*i+1]));
        A2 = __fadd_rn(A2, __fmul_rn(x[4*i+2], x[4*i+2]));
        A3 = __fadd_rn(A3, __fmul_rn(x[4*i+3], x[4*i+3]));
    }
    return __fadd_rn(__fadd_rn(A0, A1), __fadd_rn(A2, A3));
}
__device__ __forceinline__ float sumsqdiff32(const float* q, const float* h) {
    float A0, A1, A2, A3;
    {
        float d0 = __fsub_rn(q[0], h[0]), d1 = __fsub_rn(q[1], h[1]);
        float d2 = __fsub_rn(q[2], h[2]), d3 = __fsub_rn(q[3], h[3]);
        A0 = __fmul_rn(d0, d0); A1 = __fmul_rn(d1, d1);
        A2 = __fmul_rn(d2, d2); A3 = __fmul_rn(d3, d3);
    }
#pragma unroll
    for (int i = 1; i < 8; i++) {
        float e0 = __fsub_rn(q[4*i+0], h[4*i+0]), e1 = __fsub_rn(q[4*i+1], h[4*i+1]);
        float e2 = __fsub_rn(q[4*i+2], h[4*i+2]), e3 = __fsub_rn(q[4*i+3], h[4*i+3]);
        A0 = __fadd_rn(A0, __fmul_rn(e0, e0));
        A1 = __fadd_rn(A1, __fmul_rn(e1, e1));
        A2 = __fadd_rn(A2, __fmul_rn(e2, e2));
        A3 = __fadd_rn(A3, __fmul_rn(e3, e3));
    }
    return __fadd_rn(__fadd_rn(A0, A1), __fadd_rn(A2, A3));
}

extern __shared__ char smch[];

__global__ void __launch_bounds__(TPB, 2)
vq_kernel(const float* __restrict__ H, const float* __restrict__ E,
          float* __restrict__ out) {
    const int tid = threadIdx.x;

    // ---- two tokens per thread (clamped; overlaps across CTAs are benign,
    //      duplicate writes carry identical bits) ----
    int t0 = blockIdx.x * TOKPB + 2 * tid;
    if (t0 > NTOK - 2) t0 = NTOK - 2;
    const int t1 = t0 + 1;

    // h as token-pair packed u64: hh[k] = (h_t0[k], h_t1[k])
    u64 hh[DIM];
    float a0, a1;
    float h0[DIM], h1[DIM];
    {
        const float4* p0 = (const float4*)(H + (size_t)t0 * DIM);
        const float4* p1 = (const float4*)(H + (size_t)t1 * DIM);
#pragma unroll
        for (int v = 0; v < 8; v++) {
            float4 x = p0[v], y = p1[v];
            h0[4*v+0] = x.x; h0[4*v+1] = x.y; h0[4*v+2] = x.z; h0[4*v+3] = x.w;
            h1[4*v+0] = y.x; h1[4*v+1] = y.y; h1[4*v+2] = y.z; h1[4*v+3] = y.w;
            hh[4*v+0] = pk2(x.x, y.x); hh[4*v+1] = pk2(x.y, y.y);
            hh[4*v+2] = pk2(x.z, y.z); hh[4*v+3] = pk2(x.w, y.w);
        }
        a0 = sumsq32(h0);
        a1 = sumsq32(h1);
    }
    const u64 aP   = pk2(a0, a1);
    const u64 neg2 = pk2(-2.0f, -2.0f);

    const float INFP = __int_as_float(0x7f800000);
    float b0 = INFP, b1 = INFP;
    int i0 = 0, i1 = 0;

    // ---- 4 passes over quarter tables ----
#pragma unroll 1
    for (int pass = 0; pass < NPASS; pass++) {
        // build: thread tid owns local code row tid (exactly 256 codes)
        {
            const int code = pass * CPP + tid;
            float e[DIM];
            const float4* ep = (const float4*)(E + (size_t)code * DIM);
#pragma unroll
            for (int v = 0; v < 8; v++) {
                float4 x = ep[v];
                e[4*v+0] = x.x; e[4*v+1] = x.y; e[4*v+2] = x.z; e[4*v+3] = x.w;
            }
            u64* row = (u64*)(smch + tid * ROWB);
#pragma unroll
            for (int k = 0; k < DIM; k++) row[k] = pk2(e[k], e[k]);
            float nb = sumsq32(e);
            ((u64*)(smch + BN_O))[tid] = pk2(nb, nb);
        }
        __syncthreads();

        // main: 64 tiles of 4 codes
#pragma unroll 1
        for (int t = 0; t < CPP / 4; t++) {
            const ulonglong2* r0 = (const ulonglong2*)(smch + (4*t + 0) * ROWB);
            const ulonglong2* r1 = (const ulonglong2*)(smch + (4*t + 1) * ROWB);
            const ulonglong2* r2 = (const ulonglong2*)(smch + (4*t + 2) * ROWB);
            const ulonglong2* r3 = (const ulonglong2*)(smch + (4*t + 3) * ROWB);
            u64 acc0 = 0, acc1 = 0, acc2 = 0, acc3 = 0;
#pragma unroll
            for (int j = 0; j < 16; j++) {          // k = 2j, 2j+1 sequential
                ulonglong2 v0 = r0[j], v1 = r1[j], v2 = r2[j], v3 = r3[j];
                const u64 ha = hh[2*j], hb = hh[2*j + 1];
                acc0 = ffma2(v0.y, hb, ffma2(v0.x, ha, acc0));
                acc1 = ffma2(v1.y, hb, ffma2(v1.x, ha, acc1));
                acc2 = ffma2(v2.y, hb, ffma2(v2.x, ha, acc2));
                acc3 = ffma2(v3.y, hb, ffma2(v3.x, ha, acc3));
            }
            // keys packed per token-pair: kp = fl(fl(a+b) - 2*dot)
            const ulonglong2* bn = (const ulonglong2*)((u64*)(smch + BN_O) + 4*t);
            ulonglong2 nA = bn[0], nB = bn[1];
            u64 kp0 = ffma2(acc0, neg2, fadd2(aP, nA.x));
            u64 kp1 = ffma2(acc1, neg2, fadd2(aP, nA.y));
            u64 kp2 = ffma2(acc2, neg2, fadd2(aP, nB.x));
            u64 kp3 = ffma2(acc3, neg2, fadd2(aP, nB.y));
            const int cbase = pass * CPP + 4 * t;
            float x0, x1;
            upk2(kp0, x0, x1);
            if (x0 < b0) { b0 = x0; i0 = cbase; }
            if (x1 < b1) { b1 = x1; i1 = cbase; }
            upk2(kp1, x0, x1);
            if (x0 < b0) { b0 = x0; i0 = cbase + 1; }
            if (x1 < b1) { b1 = x1; i1 = cbase + 1; }
            upk2(kp2, x0, x1);
            if (x0 < b0) { b0 = x0; i0 = cbase + 2; }
            if (x1 < b1) { b1 = x1; i1 = cbase + 2; }
            upk2(kp3, x0, x1);
            if (x0 < b0) { b0 = x0; i0 = cbase + 3; }
            if (x1 < b1) { b1 = x1; i1 = cbase + 3; }
        }
        __syncthreads();   // before next pass overwrites the table
    }

    // ---- exact outputs from global E (identical fp32 math to R5) ----
#pragma unroll
    for (int tt = 0; tt < TPT; tt++) {
        const int tok = tt ? t1 : t0;
        const int bi  = tt ? i1 : i0;
        const float* h = tt ? h1 : h0;
        float q[DIM];
        const float4* qp = (const float4*)(E + (size_t)bi * DIM);
#pragma unroll
        for (int v = 0; v < 8; v++) {
            float4 x = qp[v];
            q[4*v+0] = x.x; q[4*v+1] = x.y; q[4*v+2] = x.z; q[4*v+3] = x.w;
        }
        float ss = sumsqdiff32(q, h);
        float L  = __fmul_rn(ss, 0.03125f);
        float l1 = __fmul_rn(L, 0.1f);
        float loss = __fadd_rn(l1, l1);

        float4* oq = (float4*)(out + (size_t)tok * DIM);
#pragma unroll
        for (int v = 0; v < 8; v++) {
            float4 r;
            r.x = __fadd_rn(h[4*v+0], __fsub_rn(q[4*v+0], h[4*v+0]));
            r.y = __fadd_rn(h[4*v+1], __fsub_rn(q[4*v+1], h[4*v+1]));
            r.z = __fadd_rn(h[4*v+2], __fsub_rn(q[4*v+2], h[4*v+2]));
            r.w = __fadd_rn(h[4*v+3], __fsub_rn(q[4*v+3], h[4*v+3]));
            oq[v] = r;
        }
        out[(size_t)NTOK * DIM + tok] = (float)bi;
        out[(size_t)NTOK * DIM + NTOK + tok] = loss;
    }
}

extern "C" void kernel_launch(void* const* d_in, const int* in_sizes, int n_in,
                              void* d_out, int out_size) {
    (void)in_sizes; (void)n_in; (void)out_size;
    cudaFuncSetAttribute(vq_kernel, cudaFuncAttributeMaxDynamicSharedMemorySize,
                         SMEMSZ);
    vq_kernel<<<NBLK, TPB, SMEMSZ>>>((const float*)d_in[0],
                                     (const float*)d_in[1], (float*)d_out);
}

// round 12
// speedup vs baseline: 1.2369x; 1.0723x over previous
#include <cuda_runtime.h>

// VQ-VAE quantizer, round 12: k-pair f32x2 + 14 warps/SM + margin screen
// with exact warp-cooperative rescue.
//   h: (256,512,32) f32 -> 131072 tokens x 32;  embeddings: (1024,32) f32
//   out f32: qst (131072*32) | indices (131072) | loss (131072)
//
// Model: FFMA2 pipe floor 227K cyc/SM; LDS.128 broadcast = 2 L1 wavefronts
// (calibrated R9/R11). k-pair natural-layout E @TPT=2: wf ratio 0.5 (ok),
// regs ~120 -> 14 warps/SM (vs 8 in all exact schemes). k-split dots are
// inexact vs the reference sequential chain by <4.2e-6 in the key, so the
// screen tracks (m1, m2, idx); tokens with m2 < m1 + 1e-5 get an exact
// sequential-fp32 full rescan (R5-verified expression tree, first-index
// ties). Outputs always computed with the exact reference fp32 math.

typedef unsigned long long u64;
typedef unsigned int u32;

#define DIM    32
#define NCODES 1024
#define NTOK   131072
#define TPB    448          // 14 warps
#define TPT    2
#define NBLK   148
#define TOKPB  886          // 148*886 >= NTOK; 448*2=896 >= 886 (1% clamp)
#define MARGIN 1e-5f

__device__ __forceinline__ void upk2(u64 v, float& lo, float& hi) {
    asm("mov.b64 {%0, %1}, %2;" : "=f"(lo), "=f"(hi) : "l"(v));
}
__device__ __forceinline__ u64 pk2(float lo, float hi) {
    u64 r;
    asm("mov.b64 %0, {%1, %2};" : "=l"(r) : "f"(lo), "f"(hi));
    return r;
}
__device__ __forceinline__ u64 ffma2(u64 a, u64 b, u64 c) {
    u64 d;
    asm("fma.rn.f32x2 %0, %1, %2, %3;" : "=l"(d) : "l"(a), "l"(b), "l"(c));
    return d;
}

// ||x||^2, reference-order reduction (R5-verified bit-exact).
__device__ __forceinline__ float sumsq32(const float* x) {
    float A0 = __fmul_rn(x[0], x[0]), A1 = __fmul_rn(x[1], x[1]);
    float A2 = __fmul_rn(x[2], x[2]), A3 = __fmul_rn(x[3], x[3]);
#pragma unroll
    for (int i = 1; i < 8; i++) {
        A0 = __fadd_rn(A0, __fmul_rn(x[4*i+0], x[4*i+0]));
        A1 = __fadd_rn(A1, __fmul_rn(x[4*i+1], x[4*i+1]));
        A2 = __fadd_rn(A2, __fmul_rn(x[4*i+2], x[4*i+2]));
        A3 = __fadd_rn(A3, __fmul_rn(x[4*i+3], x[4*i+3]));
    }
    return __fadd_rn(__fadd_rn(A0, A1), __fadd_rn(A2, A3));
}
__device__ __forceinline__ float sumsqdiff32(const float* q, const float* h) {
    float A0, A1, A2, A3;
    {
        float d0 = __fsub_rn(q[0], h[0]), d1 = __fsub_rn(q[1], h[1]);
        float d2 = __fsub_rn(q[2], h[2]), d3 = __fsub_rn(q[3], h[3]);
        A0 = __fmul_rn(d0, d0); A1 = __fmul_rn(d1, d1);
        A2 = __fmul_rn(d2, d2); A3 = __fmul_rn(d3, d3);
    }
#pragma unroll
    for (int i = 1; i < 8; i++) {
        float e0 = __fsub_rn(q[4*i+0], h[4*i+0]), e1 = __fsub_rn(q[4*i+1], h[4*i+1]);
        float e2 = __fsub_rn(q[4*i+2], h[4*i+2]), e3 = __fsub_rn(q[4*i+3], h[4*i+3]);
        A0 = __fadd_rn(A0, __fmul_rn(e0, e0));
        A1 = __fadd_rn(A1, __fmul_rn(e1, e1));
        A2 = __fadd_rn(A2, __fmul_rn(e2, e2));
        A3 = __fadd_rn(A3, __fmul_rn(e3, e3));
    }
    return __fadd_rn(__fadd_rn(A0, A1), __fadd_rn(A2, A3));
}

extern __shared__ float smf[];   // sE[1024][32] natural, then bn[1024]

__global__ void __launch_bounds__(TPB, 1)
vq_kernel(const float* __restrict__ H, const float* __restrict__ E,
          float* __restrict__ out) {
    float* sE = smf;
    float* bn = smf + NCODES * DIM;
    const int tid = threadIdx.x, lane = tid & 31;

    // ---- table: natural layout copy + exact norms ----
    for (int r = tid; r < NCODES; r += TPB) {
        float e[DIM];
        const float4* ep = (const float4*)(E + (size_t)r * DIM);
        float4* sp = (float4*)(sE + (size_t)r * DIM);
#pragma unroll
        for (int v = 0; v < 8; v++) {
            float4 x = ep[v];
            sp[v] = x;
            e[4*v+0] = x.x; e[4*v+1] = x.y; e[4*v+2] = x.z; e[4*v+3] = x.w;
        }
        bn[r] = sumsq32(e);
    }
    __syncthreads();

    // ---- 2 tokens per thread, k-pair packed h ----
    int t0 = blockIdx.x * TOKPB + tid * TPT;
    if (t0 > NTOK - TPT) t0 = NTOK - TPT;   // clamp: duplicate identical writes

    u64 hk[TPT][16];
    float a[TPT];
#pragma unroll
    for (int t = 0; t < TPT; t++) {
        float h[DIM];
        const float4* hp = (const float4*)(H + (size_t)(t0 + t) * DIM);
#pragma unroll
        for (int v = 0; v < 8; v++) {
            float4 x = hp[v];
            h[4*v+0] = x.x; h[4*v+1] = x.y; h[4*v+2] = x.z; h[4*v+3] = x.w;
            hk[t][2*v]   = pk2(x.x, x.y);
            hk[t][2*v+1] = pk2(x.z, x.w);
        }
        a[t] = sumsq32(h);
    }

    // ---- screen: min1 (value+idx) + streaming min2 per token ----
    const float INFP = __int_as_float(0x7f800000);
    float m1[TPT], m2[TPT];
    int ix[TPT];
#pragma unroll
    for (int t = 0; t < TPT; t++) { m1[t] = INFP; m2[t] = INFP; ix[t] = 0; }

#pragma unroll 1
    for (int c = 0; c < NCODES; c += 4) {
        const ulonglong2* r0 = (const ulonglong2*)(sE + (size_t)(c + 0) * DIM);
        const ulonglong2* r1 = (const ulonglong2*)(sE + (size_t)(c + 1) * DIM);
        const ulonglong2* r2 = (const ulonglong2*)(sE + (size_t)(c + 2) * DIM);
        const ulonglong2* r3 = (const ulonglong2*)(sE + (size_t)(c + 3) * DIM);

        u64 ac[TPT][4];
#pragma unroll
        for (int t = 0; t < TPT; t++) { ac[t][0] = 0; ac[t][1] = 0; ac[t][2] = 0; ac[t][3] = 0; }

#pragma unroll
        for (int j = 0; j < 8; j++) {     // 4 k per j (one float4 per code)
            ulonglong2 v0 = r0[j], v1 = r1[j], v2 = r2[j], v3 = r3[j];
#pragma unroll
            for (int t = 0; t < TPT; t++) {
                const u64 ha = hk[t][2*j], hb = hk[t][2*j+1];
                ac[t][0] = ffma2(v0.y, hb, ffma2(v0.x, ha, ac[t][0]));
                ac[t][1] = ffma2(v1.y, hb, ffma2(v1.x, ha, ac[t][1]));
                ac[t][2] = ffma2(v2.y, hb, ffma2(v2.x, ha, ac[t][2]));
                ac[t][3] = ffma2(v3.y, hb, ffma2(v3.x, ha, ac[t][3]));
            }
        }

        const float4 b4 = *(const float4*)(bn + c);
#pragma unroll
        for (int t = 0; t < TPT; t++) {
#pragma unroll
            for (int cc = 0; cc < 4; cc++) {
                float lo, hi;
                upk2(ac[t][cc], lo, hi);
                float dot = __fadd_rn(lo, hi);
                float key = __fmaf_rn(dot, -2.0f, __fadd_rn(a[t], (&b4.x)[cc]));
                ix[t] = (key < m1[t]) ? (c + cc) : ix[t];   // strict <: first idx
                float mx = fmaxf(m1[t], key);
                m2[t] = fminf(m2[t], mx);
                m1[t] = fminf(m1[t], key);
            }
        }
    }

    // ---- exact rescue for ambiguous tokens (m2 within margin of m1) ----
#pragma unroll
    for (int t = 0; t < TPT; t++) {
        u32 bal = __ballot_sync(0xffffffffu, m2[t] < __fadd_rn(m1[t], MARGIN));
        while (bal) {
            const int src = __ffs(bal) - 1;
            bal &= bal - 1;
            float hr[DIM];
#pragma unroll
            for (int j = 0; j < 16; j++) {
                u64 v = __shfl_sync(0xffffffffu, hk[t][j], src);
                upk2(v, hr[2*j], hr[2*j+1]);
            }
            const float at = __shfl_sync(0xffffffffu, a[t], src);
            float bd = INFP;
            int bix = 0;
#pragma unroll 1
            for (int w = 0; w < 32; w++) {
                const int code = lane + 32 * w;          // ascending per lane
                const float4* er = (const float4*)(sE + (size_t)code * DIM);
                float acc = 0.0f;                        // reference chain
#pragma unroll
                for (int v = 0; v < 8; v++) {
                    float4 x = er[v];
                    acc = __fmaf_rn(x.x, hr[4*v+0], acc);
                    acc = __fmaf_rn(x.y, hr[4*v+1], acc);
                    acc = __fmaf_rn(x.z, hr[4*v+2], acc);
                    acc = __fmaf_rn(x.w, hr[4*v+3], acc);
                }
                float dd = __fmaf_rn(acc, -2.0f, __fadd_rn(at, bn[code]));
                if (dd < bd) { bd = dd; bix = code; }
            }
#pragma unroll
            for (int o = 16; o; o >>= 1) {
                float od = __shfl_xor_sync(0xffffffffu, bd, o);
                int   oi = __shfl_xor_sync(0xffffffffu, bix, o);
                if (od < bd || (od == bd && oi < bix)) { bd = od; bix = oi; }
            }
            if (lane == src) ix[t] = bix;
        }
    }

    // ---- exact outputs (identical fp32 math to R5) ----
#pragma unroll
    for (int t = 0; t < TPT; t++) {
        const int tok = t0 + t;
        float h[DIM], q[DIM];
#pragma unroll
        for (int j = 0; j < 16; j++) upk2(hk[t][j], h[2*j], h[2*j+1]);
        const float4* qp = (const float4*)(sE + (size_t)ix[t] * DIM);
#pragma unroll
        for (int v = 0; v < 8; v++) {
            float4 x = qp[v];
            q[4*v+0] = x.x; q[4*v+1] = x.y; q[4*v+2] = x.z; q[4*v+3] = x.w;
        }
        float ss = sumsqdiff32(q, h);
        float L  = __fmul_rn(ss, 0.03125f);
        float l1 = __fmul_rn(L, 0.1f);
        float loss = __fadd_rn(l1, l1);

        float4* oq = (float4*)(out + (size_t)tok * DIM);
#pragma unroll
        for (int v = 0; v < 8; v++) {
            float4 r;
            r.x = __fadd_rn(h[4*v+0], __fsub_rn(q[4*v+0], h[4*v+0]));
            r.y = __fadd_rn(h[4*v+1], __fsub_rn(q[4*v+1], h[4*v+1]));
            r.z = __fadd_rn(h[4*v+2], __fsub_rn(q[4*v+2], h[4*v+2]));
            r.w = __fadd_rn(h[4*v+3], __fsub_rn(q[4*v+3], h[4*v+3]));
            oq[v] = r;
        }
        out[(size_t)NTOK * DIM + tok] = (float)ix[t];
        out[(size_t)NTOK * DIM + NTOK + tok] = loss;
    }
}

extern "C" void kernel_launch(void* const* d_in, const int* in_sizes, int n_in,
                              void* d_out, int out_size) {
    (void)in_sizes; (void)n_in; (void)out_size;
    size_t smem = (size_t)(NCODES * DIM + NCODES) * sizeof(float);  // 135168 B
    cudaFuncSetAttribute(vq_kernel, cudaFuncAttributeMaxDynamicSharedMemorySize,
                         (int)smem);
    vq_kernel<<<NBLK, TPB, smem>>>((const float*)d_in[0], (const float*)d_in[1],
                                   (float*)d_out);
}